// round 15
// baseline (speedup 1.0000x reference)
#include <cuda_runtime.h>
#include <cuda_fp16.h>
#include <math.h>
#include <stdint.h>

// ---------------- problem constants ----------------
#define BB   4
#define NN   2048
#define DD   768
#define HH   12
#define HDIM 64
#define RS   2304
#define MM   8192
#define KK   768
#define LOG2E 1.4426950408889634f

// ---------------- scratch ----------------
__device__ __half g_q [(size_t)BB * HH * NN * HDIM];
__device__ __half g_k [(size_t)BB * HH * NN * HDIM];
__device__ __half g_vT[(size_t)BB * HH * HDIM * NN];
__device__ __half g_z16 [(size_t)MM * DD];
__device__ __half g_att16[(size_t)MM * DD];
__device__ __half g_wq16[(size_t)RS * DD];
__device__ __half g_wm16[(size_t)DD * DD];

// ---------------- helpers ----------------
__device__ __forceinline__ uint32_t smem_u32(const void* p) {
    uint32_t a;
    asm("{ .reg .u64 t; cvta.to.shared.u64 t, %1; cvt.u32.u64 %0, t; }"
        : "=r"(a) : "l"(p));
    return a;
}
__device__ __forceinline__ void mma_f16(float* c, const uint32_t* a, const uint32_t* b) {
    asm volatile("mma.sync.aligned.m16n8k16.row.col.f32.f16.f16.f32 "
        "{%0,%1,%2,%3}, {%4,%5,%6,%7}, {%8,%9}, {%0,%1,%2,%3};"
        : "+f"(c[0]), "+f"(c[1]), "+f"(c[2]), "+f"(c[3])
        : "r"(a[0]), "r"(a[1]), "r"(a[2]), "r"(a[3]), "r"(b[0]), "r"(b[1]));
}
__device__ __forceinline__ void mma_f16acc(uint32_t* c, const uint32_t* a, const uint32_t* b) {
    asm volatile("mma.sync.aligned.m16n8k16.row.col.f16.f16.f16.f16 "
        "{%0,%1}, {%2,%3,%4,%5}, {%6,%7}, {%0,%1};"
        : "+r"(c[0]), "+r"(c[1])
        : "r"(a[0]), "r"(a[1]), "r"(a[2]), "r"(a[3]), "r"(b[0]), "r"(b[1]));
}
__device__ __forceinline__ void ldsm4(uint32_t* r, uint32_t a) {
    asm volatile("ldmatrix.sync.aligned.m8n8.x4.shared.b16 {%0,%1,%2,%3}, [%4];"
        : "=r"(r[0]), "=r"(r[1]), "=r"(r[2]), "=r"(r[3]) : "r"(a));
}
__device__ __forceinline__ void cp16(uint32_t d, const void* s) {
    asm volatile("cp.async.cg.shared.global [%0], [%1], 16;" :: "r"(d), "l"(s));
}
#define CP_COMMIT() asm volatile("cp.async.commit_group;" ::: "memory")
#define CP_WAIT0()  asm volatile("cp.async.wait_group 0;" ::: "memory")

__device__ __forceinline__ uint32_t ex2_h2(uint32_t x) {
    uint32_t y;
    asm("ex2.approx.f16x2 %0, %1;" : "=r"(y) : "r"(x));
    return y;
}

// ============================================================================
// Convert pass: z, Wqkv, Wmsa -> fp16 (single)
// ============================================================================
#define N4_Z  (MM * DD / 4)
#define N4_WQ (RS * DD / 4)
#define N4_WM (DD * DD / 4)

__global__ __launch_bounds__(256) void cvt_all(
    const float* __restrict__ z, const float* __restrict__ wq,
    const float* __restrict__ wm)
{
    int i = blockIdx.x * blockDim.x + threadIdx.x;
    const float* src;
    __half* dst;
    if (i < N4_Z)                      { src = z;  dst = g_z16; }
    else if (i < N4_Z + N4_WQ)         { src = wq; dst = g_wq16; i -= N4_Z; }
    else if (i < N4_Z + N4_WQ + N4_WM) { src = wm; dst = g_wm16; i -= N4_Z + N4_WQ; }
    else return;
    float4 v = ((const float4*)src)[i];
    __half2 a = __floats2half2_rn(v.x, v.y);
    __half2 b = __floats2half2_rn(v.z, v.w);
    uint2 p; p.x = *(uint32_t*)&a; p.y = *(uint32_t*)&b;
    ((uint2*)dst)[i] = p;
}

// ============================================================================
// GEMM (out-proj): C = A @ B^T + bias, fp32 accumulate. (unchanged)
// ============================================================================
#define G_A  0
#define G_B  10240
#define G_BUF 20480
#define G_SMEM 40960

__global__ __launch_bounds__(256, 2) void gemm_tc(
    const __half* __restrict__ A, const __half* __restrict__ B,
    const float* __restrict__ bias, float* __restrict__ C, int Nc)
{
    extern __shared__ char sm[];
    uint32_t sb = smem_u32(sm);
    const int tid = threadIdx.x, wid = tid >> 5, lane = tid & 31;
    const int g = lane >> 2, t = lane & 3;
    const int wm = wid >> 2, wn = wid & 3;
    const int row0 = blockIdx.y * 128, col0 = blockIdx.x * 128;

    const int sr = tid >> 1, sseg = (tid & 1) * 2;
    const size_t gaoff = (size_t)(row0 + sr) * KK + sseg * 8;
    const size_t gboff = (size_t)(col0 + sr) * KK + sseg * 8;
    const uint32_t soff = sr * 80 + sseg * 16;

    const uint32_t loA = (uint32_t)(((lane & 7) + ((lane >> 3) & 1) * 8) * 80 + (lane >> 4) * 16);
    const uint32_t loB = (uint32_t)(((lane & 7) + (lane >> 4) * 8) * 80 + ((lane >> 3) & 1) * 16);

    float acc[4][4][4];
    #pragma unroll
    for (int mt = 0; mt < 4; mt++)
        #pragma unroll
        for (int nt = 0; nt < 4; nt++)
            #pragma unroll
            for (int j = 0; j < 4; j++) acc[mt][nt][j] = 0.f;

    {
        uint32_t d = sb;
        cp16(d + G_A + soff,      A + gaoff);
        cp16(d + G_A + soff + 16, A + gaoff + 8);
        cp16(d + G_B + soff,      B + gboff);
        cp16(d + G_B + soff + 16, B + gboff + 8);
        CP_COMMIT();
    }

    for (int i = 0; i < KK / 32; i++) {
        CP_WAIT0();
        __syncthreads();
        if (i + 1 < KK / 32) {
            const int ke = (i + 1) * 32;
            uint32_t d = sb + ((i + 1) & 1) * G_BUF;
            cp16(d + G_A + soff,      A + gaoff + ke);
            cp16(d + G_A + soff + 16, A + gaoff + ke + 8);
            cp16(d + G_B + soff,      B + gboff + ke);
            cp16(d + G_B + soff + 16, B + gboff + ke + 8);
            CP_COMMIT();
        }
        const uint32_t ab = sb + (i & 1) * G_BUF;
        #pragma unroll
        for (int ks = 0; ks < 2; ks++) {
            uint32_t fa[4][4], fb[2][4];
            #pragma unroll
            for (int mt = 0; mt < 4; mt++)
                ldsm4(fa[mt], ab + G_A + (uint32_t)((wm * 64 + mt * 16) * 80 + ks * 32) + loA);
            #pragma unroll
            for (int np = 0; np < 2; np++)
                ldsm4(fb[np], ab + G_B + (uint32_t)((wn * 32 + np * 16) * 80 + ks * 32) + loB);
            #pragma unroll
            for (int mt = 0; mt < 4; mt++)
                #pragma unroll
                for (int nt = 0; nt < 4; nt++)
                    mma_f16(acc[mt][nt], fa[mt], &fb[nt >> 1][(nt & 1) * 2]);
        }
    }

    #pragma unroll
    for (int mt = 0; mt < 4; mt++) {
        int r = row0 + wm * 64 + mt * 16 + g;
        #pragma unroll
        for (int nt = 0; nt < 4; nt++) {
            int c = col0 + wn * 32 + nt * 8 + 2 * t;
            float2 bv = *(const float2*)&bias[c];
            float2 v0, v1;
            v0.x = acc[mt][nt][0] + bv.x; v0.y = acc[mt][nt][1] + bv.y;
            v1.x = acc[mt][nt][2] + bv.x; v1.y = acc[mt][nt][3] + bv.y;
            *(float2*)&C[(size_t)r * Nc + c]       = v0;
            *(float2*)&C[(size_t)(r + 8) * Nc + c] = v1;
        }
    }
}

// ============================================================================
// QKV GEMM: fp16 accumulators per BK=32 chunk (full-rate HMMA), promoted to
// fp32 registers each chunk. Epilogue writes q/k/v^T fp16.
// ============================================================================
__global__ __launch_bounds__(256, 2) void gemm_qkv_h(
    const __half* __restrict__ A, const __half* __restrict__ B,
    const float* __restrict__ bias)
{
    extern __shared__ char sm[];
    uint32_t sb = smem_u32(sm);
    const int tid = threadIdx.x, wid = tid >> 5, lane = tid & 31;
    const int g = lane >> 2, t = lane & 3;
    const int wm = wid >> 2, wn = wid & 3;
    const int row0 = blockIdx.y * 128, col0 = blockIdx.x * 128;

    const int sr = tid >> 1, sseg = (tid & 1) * 2;
    const size_t gaoff = (size_t)(row0 + sr) * KK + sseg * 8;
    const size_t gboff = (size_t)(col0 + sr) * KK + sseg * 8;
    const uint32_t soff = sr * 80 + sseg * 16;

    const uint32_t loA = (uint32_t)(((lane & 7) + ((lane >> 3) & 1) * 8) * 80 + (lane >> 4) * 16);
    const uint32_t loB = (uint32_t)(((lane & 7) + (lane >> 4) * 8) * 80 + ((lane >> 3) & 1) * 16);

    float accf[4][4][4];
    #pragma unroll
    for (int mt = 0; mt < 4; mt++)
        #pragma unroll
        for (int nt = 0; nt < 4; nt++)
            #pragma unroll
            for (int j = 0; j < 4; j++) accf[mt][nt][j] = 0.f;

    {
        uint32_t d = sb;
        cp16(d + G_A + soff,      A + gaoff);
        cp16(d + G_A + soff + 16, A + gaoff + 8);
        cp16(d + G_B + soff,      B + gboff);
        cp16(d + G_B + soff + 16, B + gboff + 8);
        CP_COMMIT();
    }

    for (int i = 0; i < KK / 32; i++) {
        CP_WAIT0();
        __syncthreads();
        if (i + 1 < KK / 32) {
            const int ke = (i + 1) * 32;
            uint32_t d = sb + ((i + 1) & 1) * G_BUF;
            cp16(d + G_A + soff,      A + gaoff + ke);
            cp16(d + G_A + soff + 16, A + gaoff + ke + 8);
            cp16(d + G_B + soff,      B + gboff + ke);
            cp16(d + G_B + soff + 16, B + gboff + ke + 8);
            CP_COMMIT();
        }
        const uint32_t ab = sb + (i & 1) * G_BUF;

        // fp16 accumulators for this chunk (K=32: 2 chained mmas per tile)
        uint32_t a16[4][4][2];
        #pragma unroll
        for (int mt = 0; mt < 4; mt++)
            #pragma unroll
            for (int nt = 0; nt < 4; nt++) { a16[mt][nt][0] = 0; a16[mt][nt][1] = 0; }

        #pragma unroll
        for (int ks = 0; ks < 2; ks++) {
            uint32_t fa[4][4], fb[2][4];
            #pragma unroll
            for (int mt = 0; mt < 4; mt++)
                ldsm4(fa[mt], ab + G_A + (uint32_t)((wm * 64 + mt * 16) * 80 + ks * 32) + loA);
            #pragma unroll
            for (int np = 0; np < 2; np++)
                ldsm4(fb[np], ab + G_B + (uint32_t)((wn * 32 + np * 16) * 80 + ks * 32) + loB);
            #pragma unroll
            for (int mt = 0; mt < 4; mt++)
                #pragma unroll
                for (int nt = 0; nt < 4; nt++)
                    mma_f16acc(a16[mt][nt], fa[mt], &fb[nt >> 1][(nt & 1) * 2]);
        }

        // promote chunk result to fp32
        #pragma unroll
        for (int mt = 0; mt < 4; mt++)
            #pragma unroll
            for (int nt = 0; nt < 4; nt++) {
                float2 lo = __half22float2(*(__half2*)&a16[mt][nt][0]);
                float2 hi = __half22float2(*(__half2*)&a16[mt][nt][1]);
                accf[mt][nt][0] += lo.x; accf[mt][nt][1] += lo.y;
                accf[mt][nt][2] += hi.x; accf[mt][nt][3] += hi.y;
            }
    }

    #pragma unroll
    for (int mt = 0; mt < 4; mt++) {
        int r = row0 + wm * 64 + mt * 16 + g;
        const int bb = r >> 11, nn = r & 2047;
        #pragma unroll
        for (int nt = 0; nt < 4; nt++) {
            int c = col0 + wn * 32 + nt * 8 + 2 * t;
            int h = c / 192, e = c % 192;
            float2 bv = *(const float2*)&bias[c];
            float x0 = accf[mt][nt][0] + bv.x, x1 = accf[mt][nt][1] + bv.y;
            float x2 = accf[mt][nt][2] + bv.x, x3 = accf[mt][nt][3] + bv.y;
            size_t bh = (size_t)bb * HH + h;
            if (e < 64) {
                const float sc = 0.125f * LOG2E;
                __half2 w0 = __floats2half2_rn(x0 * sc, x1 * sc);
                __half2 w1 = __floats2half2_rn(x2 * sc, x3 * sc);
                *(uint32_t*)&g_q[(bh * NN + nn) * HDIM + e]     = *(uint32_t*)&w0;
                *(uint32_t*)&g_q[(bh * NN + nn + 8) * HDIM + e] = *(uint32_t*)&w1;
            } else if (e < 128) {
                int d = e - 64;
                __half2 w0 = __floats2half2_rn(x0, x1);
                __half2 w1 = __floats2half2_rn(x2, x3);
                *(uint32_t*)&g_k[(bh * NN + nn) * HDIM + d]     = *(uint32_t*)&w0;
                *(uint32_t*)&g_k[(bh * NN + nn + 8) * HDIM + d] = *(uint32_t*)&w1;
            } else {
                int d = e - 128;
                size_t vb = (bh * HDIM + d) * NN;
                g_vT[vb + nn]           = __float2half(x0);
                g_vT[vb + NN + nn]      = __float2half(x1);
                g_vT[vb + nn + 8]       = __float2half(x2);
                g_vT[vb + NN + nn + 8]  = __float2half(x3);
            }
        }
    }
}

// ============================================================================
// Flash attention (R13 config: 256 thr / 8 warps, m16 per warp).
// S fp16-acc + f16x2 softmax; PV fp32-acc. cp.async 2-buf K/V^T.
// ============================================================================
#define AQ 0
#define AP 18432
#define AK(b) (36864 + (b) * 9216)
#define AV(b) (55296 + (b) * 9216)
#define AT_SMEM 73728

__global__ __launch_bounds__(256, 2) void attn_tc()
{
    extern __shared__ char sm[];
    uint32_t sb = smem_u32(sm);
    const int tid = threadIdx.x, wid = tid >> 5, lane = tid & 31;
    const int g = lane >> 2, t = lane & 3;
    const int b = blockIdx.z, h = blockIdx.y, q0 = blockIdx.x * 128;
    const size_t bh = (size_t)b * HH + h;

    const __half* gq = g_q + bh * NN * HDIM;
    const __half* gk = g_k + bh * NN * HDIM;
    const __half* gv = g_vT + bh * HDIM * NN;

    const int qr = tid >> 1, qc = tid & 1;
    const int kr = tid >> 2, kc = tid & 3;

    {
        const __half* qs = gq + (size_t)(q0 + qr) * HDIM + qc * 32;
        #pragma unroll
        for (int it = 0; it < 4; it++)
            cp16(sb + AQ + qr * 144 + qc * 64 + it * 16, qs + it * 8);
        const __half* ks = gk + (size_t)kr * HDIM + kc * 16;
        cp16(sb + AK(0) + kr * 144 + kc * 32,      ks);
        cp16(sb + AK(0) + kr * 144 + kc * 32 + 16, ks + 8);
        const __half* vs = gv + (size_t)kr * NN + kc * 16;
        cp16(sb + AV(0) + kr * 144 + kc * 32,      vs);
        cp16(sb + AV(0) + kr * 144 + kc * 32 + 16, vs + 8);
        CP_COMMIT();
    }

    const uint32_t loA = (uint32_t)(((lane & 7) + ((lane >> 3) & 1) * 8) * 144 + (lane >> 4) * 16);
    const uint32_t loB = (uint32_t)(((lane & 7) + (lane >> 4) * 8) * 144 + ((lane >> 3) & 1) * 16);
    const uint32_t qbase = sb + AQ + (uint32_t)(wid * 16 * 144) + loA;
    const uint32_t pbase = sb + AP + (uint32_t)(wid * 16 * 144) + loA;

    uint32_t q[4][4];
    float o[8][4];
    #pragma unroll
    for (int nt = 0; nt < 8; nt++)
        #pragma unroll
        for (int j = 0; j < 4; j++) o[nt][j] = 0.f;
    float l0 = 0.f, l1 = 0.f;

    for (int kt = 0; kt < NN / 64; kt++) {
        CP_WAIT0();
        __syncthreads();
        if (kt == 0) {
            #pragma unroll
            for (int kk = 0; kk < 4; kk++) ldsm4(q[kk], qbase + kk * 32);
        }
        if (kt + 1 < NN / 64) {
            const int buf = (kt + 1) & 1;
            const __half* ks = gk + (size_t)((kt + 1) * 64 + kr) * HDIM + kc * 16;
            cp16(sb + AK(buf) + kr * 144 + kc * 32,      ks);
            cp16(sb + AK(buf) + kr * 144 + kc * 32 + 16, ks + 8);
            const __half* vs = gv + (size_t)kr * NN + (kt + 1) * 64 + kc * 16;
            cp16(sb + AV(buf) + kr * 144 + kc * 32,      vs);
            cp16(sb + AV(buf) + kr * 144 + kc * 32 + 16, vs + 8);
            CP_COMMIT();
        }
        const uint32_t kbuf = sb + AK(kt & 1), vbuf = sb + AV(kt & 1);

        float rs0 = 0.f, rs1 = 0.f;
        #pragma unroll
        for (int np2 = 0; np2 < 2; np2++) {
            uint32_t sA[2] = {0, 0}, sB[2] = {0, 0};
            uint32_t sC[2] = {0, 0}, sD[2] = {0, 0};
            #pragma unroll
            for (int kk = 0; kk < 4; kk++) {
                uint32_t kbx[4], kby[4];
                ldsm4(kbx, kbuf + (uint32_t)((np2 * 32)      * 144 + kk * 32) + loB);
                ldsm4(kby, kbuf + (uint32_t)((np2 * 32 + 16) * 144 + kk * 32) + loB);
                mma_f16acc(sA, q[kk], &kbx[0]);
                mma_f16acc(sC, q[kk], &kby[0]);
                mma_f16acc(sB, q[kk], &kbx[2]);
                mma_f16acc(sD, q[kk], &kby[2]);
            }
            #define SOFT_BLK(sacc, colbase) do {                                       \
                uint32_t p0 = ex2_h2(sacc[0]);                                         \
                uint32_t p1 = ex2_h2(sacc[1]);                                         \
                float2 f0 = __half22float2(*(__half2*)&p0);                            \
                float2 f1 = __half22float2(*(__half2*)&p1);                            \
                rs0 += f0.x + f0.y; rs1 += f1.x + f1.y;                                \
                uint32_t off = (uint32_t)((wid * 16 + g) * 144 + ((colbase) + 2 * t) * 2); \
                *(uint32_t*)(sm + AP + off)           = p0;                            \
                *(uint32_t*)(sm + AP + off + 8 * 144) = p1;                            \
            } while (0)
            SOFT_BLK(sA, np2 * 32);
            SOFT_BLK(sB, np2 * 32 + 8);
            SOFT_BLK(sC, np2 * 32 + 16);
            SOFT_BLK(sD, np2 * 32 + 24);
        }
        rs0 += __shfl_xor_sync(0xffffffffu, rs0, 1);
        rs0 += __shfl_xor_sync(0xffffffffu, rs0, 2);
        rs1 += __shfl_xor_sync(0xffffffffu, rs1, 1);
        rs1 += __shfl_xor_sync(0xffffffffu, rs1, 2);
        l0 += rs0; l1 += rs1;
        __syncwarp();

        #pragma unroll
        for (int kk = 0; kk < 4; kk++) {
            uint32_t pa[4];
            ldsm4(pa, pbase + kk * 32);
            #pragma unroll
            for (int np = 0; np < 4; np++) {
                uint32_t vb[4];
                ldsm4(vb, vbuf + (uint32_t)(np * 16 * 144 + kk * 32) + loB);
                mma_f16(o[2 * np],     pa, &vb[0]);
                mma_f16(o[2 * np + 1], pa, &vb[2]);
            }
        }
    }

    const float inv0 = 1.0f / l0, inv1 = 1.0f / l1;
    const int r0 = q0 + wid * 16 + g;
    const size_t base0 = ((size_t)b * NN + r0) * DD + h * HDIM;
    const size_t base1 = base0 + (size_t)8 * DD;
    #pragma unroll
    for (int nt = 0; nt < 8; nt++) {
        int c = nt * 8 + 2 * t;
        __half2 w0 = __floats2half2_rn(o[nt][0] * inv0, o[nt][1] * inv0);
        __half2 w1 = __floats2half2_rn(o[nt][2] * inv1, o[nt][3] * inv1);
        *(uint32_t*)&g_att16[base0 + c] = *(uint32_t*)&w0;
        *(uint32_t*)&g_att16[base1 + c] = *(uint32_t*)&w1;
    }
}

// ---------------------------------------------------------------------------
extern "C" void kernel_launch(void* const* d_in, const int* in_sizes, int n_in,
                              void* d_out, int out_size)
{
    const float* z    = (const float*)d_in[0];
    const float* Wqkv = (const float*)d_in[1];
    const float* bqkv = (const float*)d_in[2];
    const float* Wmsa = (const float*)d_in[3];
    const float* bmsa = (const float*)d_in[4];
    float* out = (float*)d_out;

    __half *z16, *att16, *wq16, *wm16;
    cudaGetSymbolAddress((void**)&z16,   g_z16);
    cudaGetSymbolAddress((void**)&att16, g_att16);
    cudaGetSymbolAddress((void**)&wq16,  g_wq16);
    cudaGetSymbolAddress((void**)&wm16,  g_wm16);

    cudaFuncSetAttribute(gemm_tc,    cudaFuncAttributeMaxDynamicSharedMemorySize, G_SMEM);
    cudaFuncSetAttribute(gemm_qkv_h, cudaFuncAttributeMaxDynamicSharedMemorySize, G_SMEM);
    cudaFuncSetAttribute(attn_tc,    cudaFuncAttributeMaxDynamicSharedMemorySize, AT_SMEM);

    const int total4 = N4_Z + N4_WQ + N4_WM;
    cvt_all<<<(total4 + 255) / 256, 256>>>(z, Wqkv, Wmsa);

    gemm_qkv_h<<<dim3(RS / 128, MM / 128), 256, G_SMEM>>>(z16, wq16, bqkv);
    attn_tc<<<dim3(NN / 128, HH, BB), 256, AT_SMEM>>>();
    gemm_tc<<<dim3(DD / 128, MM / 128), 256, G_SMEM>>>(att16, wm16, bmsa,
                                                       out, DD);
}

// round 16
// speedup vs baseline: 1.7412x; 1.7412x over previous
#include <cuda_runtime.h>
#include <cuda_fp16.h>
#include <math.h>
#include <stdint.h>

// ---------------- problem constants ----------------
#define BB   4
#define NN   2048
#define DD   768
#define HH   12
#define HDIM 64
#define RS   2304
#define MM   8192
#define KK   768
#define LOG2E 1.4426950408889634f

// ---------------- scratch ----------------
__device__ __half g_q [(size_t)BB * HH * NN * HDIM];
__device__ __half g_k [(size_t)BB * HH * NN * HDIM];
__device__ __half g_vT[(size_t)BB * HH * HDIM * NN];
__device__ __half g_z16 [(size_t)MM * DD];
__device__ __half g_att16[(size_t)MM * DD];
__device__ __half g_wq16[(size_t)RS * DD];
__device__ __half g_wm16[(size_t)DD * DD];

// ---------------- helpers ----------------
__device__ __forceinline__ uint32_t smem_u32(const void* p) {
    uint32_t a;
    asm("{ .reg .u64 t; cvta.to.shared.u64 t, %1; cvt.u32.u64 %0, t; }"
        : "=r"(a) : "l"(p));
    return a;
}
__device__ __forceinline__ void mma_f16(float* c, const uint32_t* a, const uint32_t* b) {
    asm volatile("mma.sync.aligned.m16n8k16.row.col.f32.f16.f16.f32 "
        "{%0,%1,%2,%3}, {%4,%5,%6,%7}, {%8,%9}, {%0,%1,%2,%3};"
        : "+f"(c[0]), "+f"(c[1]), "+f"(c[2]), "+f"(c[3])
        : "r"(a[0]), "r"(a[1]), "r"(a[2]), "r"(a[3]), "r"(b[0]), "r"(b[1]));
}
__device__ __forceinline__ void mma_f16acc(uint32_t* c, const uint32_t* a, const uint32_t* b) {
    asm volatile("mma.sync.aligned.m16n8k16.row.col.f16.f16.f16.f16 "
        "{%0,%1}, {%2,%3,%4,%5}, {%6,%7}, {%0,%1};"
        : "+r"(c[0]), "+r"(c[1])
        : "r"(a[0]), "r"(a[1]), "r"(a[2]), "r"(a[3]), "r"(b[0]), "r"(b[1]));
}
__device__ __forceinline__ void ldsm4(uint32_t* r, uint32_t a) {
    asm volatile("ldmatrix.sync.aligned.m8n8.x4.shared.b16 {%0,%1,%2,%3}, [%4];"
        : "=r"(r[0]), "=r"(r[1]), "=r"(r[2]), "=r"(r[3]) : "r"(a));
}
__device__ __forceinline__ void cp16(uint32_t d, const void* s) {
    asm volatile("cp.async.cg.shared.global [%0], [%1], 16;" :: "r"(d), "l"(s));
}
#define CP_COMMIT() asm volatile("cp.async.commit_group;" ::: "memory")
#define CP_WAIT0()  asm volatile("cp.async.wait_group 0;" ::: "memory")

__device__ __forceinline__ uint32_t ex2_h2(uint32_t x) {
    uint32_t y;
    asm("ex2.approx.f16x2 %0, %1;" : "=r"(y) : "r"(x));
    return y;
}

// ============================================================================
// Convert pass: z, Wqkv, Wmsa -> fp16 (single)
// ============================================================================
#define N4_Z  (MM * DD / 4)
#define N4_WQ (RS * DD / 4)
#define N4_WM (DD * DD / 4)

__global__ __launch_bounds__(256) void cvt_all(
    const float* __restrict__ z, const float* __restrict__ wq,
    const float* __restrict__ wm)
{
    int i = blockIdx.x * blockDim.x + threadIdx.x;
    const float* src;
    __half* dst;
    if (i < N4_Z)                      { src = z;  dst = g_z16; }
    else if (i < N4_Z + N4_WQ)         { src = wq; dst = g_wq16; i -= N4_Z; }
    else if (i < N4_Z + N4_WQ + N4_WM) { src = wm; dst = g_wm16; i -= N4_Z + N4_WQ; }
    else return;
    float4 v = ((const float4*)src)[i];
    __half2 a = __floats2half2_rn(v.x, v.y);
    __half2 b = __floats2half2_rn(v.z, v.w);
    uint2 p; p.x = *(uint32_t*)&a; p.y = *(uint32_t*)&b;
    ((uint2*)dst)[i] = p;
}

// ============================================================================
// GEMM (R13): C = A @ B^T + bias, fp32 accumulate.
// mode 0: fp32 C + bias. mode 1: QKV epilogue (q/k/v^T fp16).
// ============================================================================
#define G_A  0
#define G_B  10240
#define G_BUF 20480
#define G_SMEM 40960

__global__ __launch_bounds__(256, 2) void gemm_tc(
    const __half* __restrict__ A, const __half* __restrict__ B,
    const float* __restrict__ bias, float* __restrict__ C, int Nc, int mode)
{
    extern __shared__ char sm[];
    uint32_t sb = smem_u32(sm);
    const int tid = threadIdx.x, wid = tid >> 5, lane = tid & 31;
    const int g = lane >> 2, t = lane & 3;
    const int wm = wid >> 2, wn = wid & 3;
    const int row0 = blockIdx.y * 128, col0 = blockIdx.x * 128;

    const int sr = tid >> 1, sseg = (tid & 1) * 2;
    const size_t gaoff = (size_t)(row0 + sr) * KK + sseg * 8;
    const size_t gboff = (size_t)(col0 + sr) * KK + sseg * 8;
    const uint32_t soff = sr * 80 + sseg * 16;

    const uint32_t loA = (uint32_t)(((lane & 7) + ((lane >> 3) & 1) * 8) * 80 + (lane >> 4) * 16);
    const uint32_t loB = (uint32_t)(((lane & 7) + (lane >> 4) * 8) * 80 + ((lane >> 3) & 1) * 16);

    float acc[4][4][4];
    #pragma unroll
    for (int mt = 0; mt < 4; mt++)
        #pragma unroll
        for (int nt = 0; nt < 4; nt++)
            #pragma unroll
            for (int j = 0; j < 4; j++) acc[mt][nt][j] = 0.f;

    {
        uint32_t d = sb;
        cp16(d + G_A + soff,      A + gaoff);
        cp16(d + G_A + soff + 16, A + gaoff + 8);
        cp16(d + G_B + soff,      B + gboff);
        cp16(d + G_B + soff + 16, B + gboff + 8);
        CP_COMMIT();
    }

    for (int i = 0; i < KK / 32; i++) {
        CP_WAIT0();
        __syncthreads();
        if (i + 1 < KK / 32) {
            const int ke = (i + 1) * 32;
            uint32_t d = sb + ((i + 1) & 1) * G_BUF;
            cp16(d + G_A + soff,      A + gaoff + ke);
            cp16(d + G_A + soff + 16, A + gaoff + ke + 8);
            cp16(d + G_B + soff,      B + gboff + ke);
            cp16(d + G_B + soff + 16, B + gboff + ke + 8);
            CP_COMMIT();
        }
        const uint32_t ab = sb + (i & 1) * G_BUF;
        #pragma unroll
        for (int ks = 0; ks < 2; ks++) {
            uint32_t fa[4][4], fb[2][4];
            #pragma unroll
            for (int mt = 0; mt < 4; mt++)
                ldsm4(fa[mt], ab + G_A + (uint32_t)((wm * 64 + mt * 16) * 80 + ks * 32) + loA);
            #pragma unroll
            for (int np = 0; np < 2; np++)
                ldsm4(fb[np], ab + G_B + (uint32_t)((wn * 32 + np * 16) * 80 + ks * 32) + loB);
            #pragma unroll
            for (int mt = 0; mt < 4; mt++)
                #pragma unroll
                for (int nt = 0; nt < 4; nt++)
                    mma_f16(acc[mt][nt], fa[mt], &fb[nt >> 1][(nt & 1) * 2]);
        }
    }

    #pragma unroll
    for (int mt = 0; mt < 4; mt++) {
        int r = row0 + wm * 64 + mt * 16 + g;
        if (mode == 0) {
            #pragma unroll
            for (int nt = 0; nt < 4; nt++) {
                int c = col0 + wn * 32 + nt * 8 + 2 * t;
                float2 bv = *(const float2*)&bias[c];
                float2 v0, v1;
                v0.x = acc[mt][nt][0] + bv.x; v0.y = acc[mt][nt][1] + bv.y;
                v1.x = acc[mt][nt][2] + bv.x; v1.y = acc[mt][nt][3] + bv.y;
                *(float2*)&C[(size_t)r * Nc + c]       = v0;
                *(float2*)&C[(size_t)(r + 8) * Nc + c] = v1;
            }
        } else {
            const int bb = r >> 11, nn = r & 2047;
            #pragma unroll
            for (int nt = 0; nt < 4; nt++) {
                int c = col0 + wn * 32 + nt * 8 + 2 * t;
                int h = c / 192, e = c % 192;
                float2 bv = *(const float2*)&bias[c];
                float x0 = acc[mt][nt][0] + bv.x, x1 = acc[mt][nt][1] + bv.y;
                float x2 = acc[mt][nt][2] + bv.x, x3 = acc[mt][nt][3] + bv.y;
                size_t bh = (size_t)bb * HH + h;
                if (e < 64) {
                    const float sc = 0.125f * LOG2E;
                    __half2 w0 = __floats2half2_rn(x0 * sc, x1 * sc);
                    __half2 w1 = __floats2half2_rn(x2 * sc, x3 * sc);
                    *(uint32_t*)&g_q[(bh * NN + nn) * HDIM + e]     = *(uint32_t*)&w0;
                    *(uint32_t*)&g_q[(bh * NN + nn + 8) * HDIM + e] = *(uint32_t*)&w1;
                } else if (e < 128) {
                    int d = e - 64;
                    __half2 w0 = __floats2half2_rn(x0, x1);
                    __half2 w1 = __floats2half2_rn(x2, x3);
                    *(uint32_t*)&g_k[(bh * NN + nn) * HDIM + d]     = *(uint32_t*)&w0;
                    *(uint32_t*)&g_k[(bh * NN + nn + 8) * HDIM + d] = *(uint32_t*)&w1;
                } else {
                    int d = e - 128;
                    size_t vb = (bh * HDIM + d) * NN;
                    g_vT[vb + nn]           = __float2half(x0);
                    g_vT[vb + NN + nn]      = __float2half(x1);
                    g_vT[vb + nn + 8]       = __float2half(x2);
                    g_vT[vb + NN + nn + 8]  = __float2half(x3);
                }
            }
        }
    }
}

// ============================================================================
// Flash attention v9: P never touches smem. S fp16-acc fragments are
// softmaxed in-register (ex2.f16x2) and fed DIRECTLY as the A-operand of the
// PV mma (fragment-layout identity). No P buffer, no syncwarp, no P LDSM.
// ============================================================================
#define AQ 0                              // Q fp16: 128 x 144B
#define AK(b) (18432 + (b) * 9216)        // K fp16: 64 x 144B, 2 bufs
#define AV(b) (36864 + (b) * 9216)        // V^T fp16: 64 x 144B, 2 bufs
#define AT_SMEM 55296

__global__ __launch_bounds__(256, 2) void attn_tc()
{
    extern __shared__ char sm[];
    uint32_t sb = smem_u32(sm);
    const int tid = threadIdx.x, wid = tid >> 5, lane = tid & 31;
    const int b = blockIdx.z, h = blockIdx.y, q0 = blockIdx.x * 128;
    const size_t bh = (size_t)b * HH + h;

    const __half* gq = g_q + bh * NN * HDIM;
    const __half* gk = g_k + bh * NN * HDIM;
    const __half* gv = g_vT + bh * HDIM * NN;

    const int qr = tid >> 1, qc = tid & 1;
    const int kr = tid >> 2, kc = tid & 3;

    {
        const __half* qs = gq + (size_t)(q0 + qr) * HDIM + qc * 32;
        #pragma unroll
        for (int it = 0; it < 4; it++)
            cp16(sb + AQ + qr * 144 + qc * 64 + it * 16, qs + it * 8);
        const __half* ks = gk + (size_t)kr * HDIM + kc * 16;
        cp16(sb + AK(0) + kr * 144 + kc * 32,      ks);
        cp16(sb + AK(0) + kr * 144 + kc * 32 + 16, ks + 8);
        const __half* vs = gv + (size_t)kr * NN + kc * 16;
        cp16(sb + AV(0) + kr * 144 + kc * 32,      vs);
        cp16(sb + AV(0) + kr * 144 + kc * 32 + 16, vs + 8);
        CP_COMMIT();
    }

    const uint32_t loA = (uint32_t)(((lane & 7) + ((lane >> 3) & 1) * 8) * 144 + (lane >> 4) * 16);
    const uint32_t loB = (uint32_t)(((lane & 7) + (lane >> 4) * 8) * 144 + ((lane >> 3) & 1) * 16);
    const uint32_t qbase = sb + AQ + (uint32_t)(wid * 16 * 144) + loA;

    uint32_t q[4][4];
    float o[8][4];
    #pragma unroll
    for (int nt = 0; nt < 8; nt++)
        #pragma unroll
        for (int j = 0; j < 4; j++) o[nt][j] = 0.f;
    float l0 = 0.f, l1 = 0.f;

    for (int kt = 0; kt < NN / 64; kt++) {
        CP_WAIT0();
        __syncthreads();
        if (kt == 0) {
            #pragma unroll
            for (int kk = 0; kk < 4; kk++) ldsm4(q[kk], qbase + kk * 32);
        }
        if (kt + 1 < NN / 64) {
            const int buf = (kt + 1) & 1;
            const __half* ks = gk + (size_t)((kt + 1) * 64 + kr) * HDIM + kc * 16;
            cp16(sb + AK(buf) + kr * 144 + kc * 32,      ks);
            cp16(sb + AK(buf) + kr * 144 + kc * 32 + 16, ks + 8);
            const __half* vs = gv + (size_t)kr * NN + (kt + 1) * 64 + kc * 16;
            cp16(sb + AV(buf) + kr * 144 + kc * 32,      vs);
            cp16(sb + AV(buf) + kr * 144 + kc * 32 + 16, vs + 8);
            CP_COMMIT();
        }
        const uint32_t kbuf = sb + AK(kt & 1), vbuf = sb + AV(kt & 1);

        // per np2 (32 kv cols): S (fp16 acc) -> softmax in regs -> PV directly
        #pragma unroll
        for (int np2 = 0; np2 < 2; np2++) {
            uint32_t sA[2] = {0, 0}, sB[2] = {0, 0};
            uint32_t sC[2] = {0, 0}, sD[2] = {0, 0};
            #pragma unroll
            for (int kk = 0; kk < 4; kk++) {
                uint32_t kbx[4], kby[4];
                ldsm4(kbx, kbuf + (uint32_t)((np2 * 32)      * 144 + kk * 32) + loB);
                ldsm4(kby, kbuf + (uint32_t)((np2 * 32 + 16) * 144 + kk * 32) + loB);
                mma_f16acc(sA, q[kk], &kbx[0]);
                mma_f16acc(sC, q[kk], &kby[0]);
                mma_f16acc(sB, q[kk], &kbx[2]);
                mma_f16acc(sD, q[kk], &kby[2]);
            }
            // softmax in registers; assemble PV A-fragments directly
            // pf0 covers kv [np2*32 .. +15]   (sA: cols 0-7, sB: cols 8-15)
            // pf1 covers kv [np2*32+16 .. +31](sC, sD)
            uint32_t pf0[4], pf1[4];
            pf0[0] = ex2_h2(sA[0]); pf0[1] = ex2_h2(sA[1]);
            pf0[2] = ex2_h2(sB[0]); pf0[3] = ex2_h2(sB[1]);
            pf1[0] = ex2_h2(sC[0]); pf1[1] = ex2_h2(sC[1]);
            pf1[2] = ex2_h2(sD[0]); pf1[3] = ex2_h2(sD[1]);
            #pragma unroll
            for (int j = 0; j < 4; j += 2) {   // j=0: row g regs, j+... (c0 rows g, c1 rows g+8)
                float2 f;
                f = __half22float2(*(__half2*)&pf0[j]);     l0 += f.x + f.y;
                f = __half22float2(*(__half2*)&pf0[j + 1]); l1 += f.x + f.y;
                f = __half22float2(*(__half2*)&pf1[j]);     l0 += f.x + f.y;
                f = __half22float2(*(__half2*)&pf1[j + 1]); l1 += f.x + f.y;
            }
            // O += P @ V for this np2's two k16 blocks
            #pragma unroll
            for (int j = 0; j < 2; j++) {
                const uint32_t* pf = (j == 0) ? pf0 : pf1;
                const uint32_t kkcol = (uint32_t)((np2 * 2 + j) * 32);
                #pragma unroll
                for (int np = 0; np < 4; np++) {
                    uint32_t vb[4];
                    ldsm4(vb, vbuf + (uint32_t)(np * 16 * 144) + kkcol + loB);
                    mma_f16(o[2 * np],     pf, &vb[0]);
                    mma_f16(o[2 * np + 1], pf, &vb[2]);
                }
            }
        }
    }

    // l0 currently sums rows g (c0 lanes) over this thread's 2 cols; reduce quad
    l0 += __shfl_xor_sync(0xffffffffu, l0, 1);
    l0 += __shfl_xor_sync(0xffffffffu, l0, 2);
    l1 += __shfl_xor_sync(0xffffffffu, l1, 1);
    l1 += __shfl_xor_sync(0xffffffffu, l1, 2);

    const int g = lane >> 2, t = lane & 3;
    const float inv0 = 1.0f / l0, inv1 = 1.0f / l1;
    const int r0 = q0 + wid * 16 + g;
    const size_t base0 = ((size_t)b * NN + r0) * DD + h * HDIM;
    const size_t base1 = base0 + (size_t)8 * DD;
    #pragma unroll
    for (int nt = 0; nt < 8; nt++) {
        int c = nt * 8 + 2 * t;
        __half2 w0 = __floats2half2_rn(o[nt][0] * inv0, o[nt][1] * inv0);
        __half2 w1 = __floats2half2_rn(o[nt][2] * inv1, o[nt][3] * inv1);
        *(uint32_t*)&g_att16[base0 + c] = *(uint32_t*)&w0;
        *(uint32_t*)&g_att16[base1 + c] = *(uint32_t*)&w1;
    }
}

// ---------------------------------------------------------------------------
extern "C" void kernel_launch(void* const* d_in, const int* in_sizes, int n_in,
                              void* d_out, int out_size)
{
    const float* z    = (const float*)d_in[0];
    const float* Wqkv = (const float*)d_in[1];
    const float* bqkv = (const float*)d_in[2];
    const float* Wmsa = (const float*)d_in[3];
    const float* bmsa = (const float*)d_in[4];
    float* out = (float*)d_out;

    __half *z16, *att16, *wq16, *wm16;
    cudaGetSymbolAddress((void**)&z16,   g_z16);
    cudaGetSymbolAddress((void**)&att16, g_att16);
    cudaGetSymbolAddress((void**)&wq16,  g_wq16);
    cudaGetSymbolAddress((void**)&wm16,  g_wm16);

    cudaFuncSetAttribute(gemm_tc, cudaFuncAttributeMaxDynamicSharedMemorySize, G_SMEM);
    cudaFuncSetAttribute(attn_tc, cudaFuncAttributeMaxDynamicSharedMemorySize, AT_SMEM);

    const int total4 = N4_Z + N4_WQ + N4_WM;
    cvt_all<<<(total4 + 255) / 256, 256>>>(z, Wqkv, Wmsa);

    gemm_tc<<<dim3(RS / 128, MM / 128), 256, G_SMEM>>>(z16, wq16, bqkv,
                                                       out, RS, 1);
    attn_tc<<<dim3(NN / 128, HH, BB), 256, AT_SMEM>>>();
    gemm_tc<<<dim3(DD / 128, MM / 128), 256, G_SMEM>>>(att16, wm16, bmsa,
                                                       out, DD, 0);
}